// round 7
// baseline (speedup 1.0000x reference)
#include <cuda_runtime.h>
#include <cuda_bf16.h>
#include <cstdint>
#include <math.h>

// Problem constants
#define BB   4
#define HH   1024
#define LL   8192
#define KD   64
#define KLEN 512      // KD * 2^(NS-1)

// ---------------- static device scratch ----------------
__device__ float g_k[HH * KLEN];                         // normalized kernel [h][t]
__device__ float g_v[(size_t)BB * HH * LL];              // gelu(conv + u*D) [b][h][l]  (128 MB)
__device__ __nv_bfloat16 g_vth[(size_t)BB * LL * HH];    // v transposed hi  [b][l][h]  (64 MB)
__device__ __nv_bfloat16 g_vtl[(size_t)BB * LL * HH];    // v transposed lo  [b][l][h]  (64 MB)
__device__ __nv_bfloat16 g_Wh[HH * HH];                  // W hi [o][h]
__device__ __nv_bfloat16 g_Wl[HH * HH];                  // W lo [o][h]

// ---------------- f32x2 packed helpers ----------------
__device__ __forceinline__ unsigned long long pk2(float a, float b) {
    unsigned long long r;
    asm("mov.b64 %0, {%1, %2};" : "=l"(r) : "f"(a), "f"(b));
    return r;
}
__device__ __forceinline__ void upk2(unsigned long long v, float& a, float& b) {
    asm("mov.b64 {%0, %1}, %2;" : "=f"(a), "=f"(b) : "l"(v));
}
__device__ __forceinline__ void fma2(unsigned long long& d, unsigned long long a,
                                     unsigned long long b) {
    asm("fma.rn.f32x2 %0, %1, %2, %0;" : "+l"(d) : "l"(a), "l"(b));
}

// ---------------- PTX helpers (baseline ISA only) ----------------
__device__ __forceinline__ uint32_t smem_u32(const void* p) {
    uint32_t a;
    asm("{ .reg .u64 t; cvta.to.shared.u64 t, %1; cvt.u32.u64 %0, t; }" : "=r"(a) : "l"(p));
    return a;
}
__device__ __forceinline__ void cp_async16(uint32_t sa, const void* g) {
    asm volatile("cp.async.cg.shared.global [%0], [%1], 16;" :: "r"(sa), "l"(g));
}
__device__ __forceinline__ void cp_commit() {
    asm volatile("cp.async.commit_group;" ::: "memory");
}
template<int N> __device__ __forceinline__ void cp_wait() {
    asm volatile("cp.async.wait_group %0;" :: "n"(N) : "memory");
}
__device__ __forceinline__ void ldmx4(uint32_t& r0, uint32_t& r1, uint32_t& r2, uint32_t& r3,
                                      uint32_t addr) {
    asm volatile("ldmatrix.sync.aligned.m8n8.x4.shared.b16 {%0,%1,%2,%3}, [%4];"
                 : "=r"(r0), "=r"(r1), "=r"(r2), "=r"(r3) : "r"(addr));
}
__device__ __forceinline__ void mma16816(float* c, const uint32_t* a, uint32_t b0, uint32_t b1) {
    asm volatile(
        "mma.sync.aligned.m16n8k16.row.col.f32.bf16.bf16.f32 "
        "{%0,%1,%2,%3}, {%4,%5,%6,%7}, {%8,%9}, {%0,%1,%2,%3};"
        : "+f"(c[0]), "+f"(c[1]), "+f"(c[2]), "+f"(c[3])
        : "r"(a[0]), "r"(a[1]), "r"(a[2]), "r"(a[3]), "r"(b0), "r"(b1));
}

// ============================================================
// Kernel 1: build combined, normalized conv kernel per head.
// ============================================================
__global__ void __launch_bounds__(128) build_k_kernel(
    const float* __restrict__ k0, const float* __restrict__ k1,
    const float* __restrict__ k2, const float* __restrict__ k3)
{
    int h   = blockIdx.x;
    int tid = threadIdx.x;
    const float* ks[4] = { k0 + h * KD, k1 + h * KD, k2 + h * KD, k3 + h * KD };

    float vals[4];
    float ss = 0.0f;
#pragma unroll
    for (int r = 0; r < 4; r++) {
        int t = tid + r * 128;
        float acc = 0.0f;
#pragma unroll
        for (int i = 0; i < 4; i++) {
            int len = KD << i;
            if (t < len) {
                float s = (float)(1 << i);
                float coord = (t + 0.5f) / s - 0.5f;
                coord = fminf(fmaxf(coord, 0.0f), 63.0f);
                int lo  = (int)floorf(coord);
                float w = coord - (float)lo;
                int hi  = min(lo + 1, 63);
                float val = ks[i][lo] * (1.0f - w) + ks[i][hi] * w;
                acc += val * (float)(1 << (3 - i));
            }
        }
        vals[r] = acc;
        ss += acc * acc;
    }

    __shared__ float red[128];
    red[tid] = ss;
    __syncthreads();
    for (int s = 64; s > 0; s >>= 1) {
        if (tid < s) red[tid] += red[tid + s];
        __syncthreads();
    }
    float inv = 1.0f / sqrtf(red[0]);
#pragma unroll
    for (int r = 0; r < 4; r++)
        g_k[h * KLEN + tid + r * 128] = vals[r] * inv;
}

// ============================================================
// Kernel 2: causal 512-tap conv + u*D + exact GELU -> g_v  (proven)
// ============================================================
#define CTILE 2048

__global__ void __launch_bounds__(256) conv_gelu_kernel(
    const float* __restrict__ u, const float* __restrict__ D)
{
    int bh  = blockIdx.y;
    int h   = bh & (HH - 1);
    int l0  = blockIdx.x * CTILE;
    int tid = threadIdx.x;

    __shared__ float k_s[KLEN];
    __shared__ float u_s[KLEN + CTILE];

    const float* ub = u + (size_t)bh * LL;

#pragma unroll
    for (int i = 0; i < 2; i++)
        k_s[tid + i * 256] = g_k[h * KLEN + tid + i * 256];
#pragma unroll
    for (int i = 0; i < 10; i++) {
        int idx = tid + i * 256;
        int g = l0 - KLEN + idx;
        u_s[idx] = (g >= 0) ? ub[g] : 0.0f;
    }
    __syncthreads();

    int li = tid * 8;
    const float* up = u_s + KLEN + li;

    unsigned long long acc2[4];
#pragma unroll
    for (int p = 0; p < 4; p++) acc2[p] = 0ull;

#pragma unroll 2
    for (int t = 0; t < KLEN; t += 4) {
        float4 k4 = *reinterpret_cast<const float4*>(k_s + t);
        float uv[12];
        *reinterpret_cast<float4*>(uv)     = *reinterpret_cast<const float4*>(up - t - 4);
        *reinterpret_cast<float4*>(uv + 4) = *reinterpret_cast<const float4*>(up - t);
        *reinterpret_cast<float4*>(uv + 8) = *reinterpret_cast<const float4*>(up - t + 4);
        const unsigned long long* uvl = reinterpret_cast<const unsigned long long*>(uv);

        unsigned long long kp0 = pk2(k4.x, k4.x);
        unsigned long long kp1 = pk2(k4.y, k4.y);
        unsigned long long kp2 = pk2(k4.z, k4.z);
        unsigned long long kp3 = pk2(k4.w, k4.w);
        unsigned long long po[5];
#pragma unroll
        for (int q = 0; q < 5; q++) po[q] = pk2(uv[2 * q + 1], uv[2 * q + 2]);

#pragma unroll
        for (int p = 0; p < 4; p++) {
            fma2(acc2[p], kp0, uvl[p + 2]);
            fma2(acc2[p], kp1, po[p + 1]);
            fma2(acc2[p], kp2, uvl[p + 1]);
            fma2(acc2[p], kp3, po[p]);
        }
    }

    float res[8];
#pragma unroll
    for (int p = 0; p < 4; p++) upk2(acc2[p], res[2 * p], res[2 * p + 1]);

    float d = D[h];
    float4 uc0 = *reinterpret_cast<const float4*>(up);
    float4 uc1 = *reinterpret_cast<const float4*>(up + 4);
    float uu[8] = { uc0.x, uc0.y, uc0.z, uc0.w, uc1.x, uc1.y, uc1.z, uc1.w };

    float outv[8];
#pragma unroll
    for (int r = 0; r < 8; r++) {
        float x = res[r] + uu[r] * d;
        outv[r] = 0.5f * x * (1.0f + erff(x * 0.70710678118654752f));
    }

    float* vb = g_v + (size_t)bh * LL + l0 + li;
    *reinterpret_cast<float4*>(vb)     = make_float4(outv[0], outv[1], outv[2], outv[3]);
    *reinterpret_cast<float4*>(vb + 4) = make_float4(outv[4], outv[5], outv[6], outv[7]);
}

// ============================================================
// Kernel 3: W f32 -> bf16 hi/lo (same layout [o][h])
// ============================================================
__global__ void __launch_bounds__(256) wconv_kernel(const float* __restrict__ W)
{
    int base = (blockIdx.x * 256 + threadIdx.x) * 4;
#pragma unroll
    for (int i = 0; i < 4; i++) {
        float x = W[base + i];
        __nv_bfloat16 h = __float2bfloat16(x);
        __nv_bfloat16 l = __float2bfloat16(x - __bfloat162float(h));
        g_Wh[base + i] = h;
        g_Wl[base + i] = l;
    }
}

// ============================================================
// Kernel 4: transpose + split-convert v[b][h][l] f32 -> v_t hi/lo bf16 [b][l][h]
// ============================================================
__global__ void __launch_bounds__(256) transpose_convert_kernel()
{
    int b  = blockIdx.z;
    int h0 = blockIdx.y * 64;
    int l0 = blockIdx.x * 64;
    int tid = threadIdx.x;

    __shared__ float t[64][65];

    int hi_ = tid >> 4;
    int li4 = (tid & 15) * 4;
    const float* src = g_v + ((size_t)(b * HH + h0)) * LL + l0;
#pragma unroll
    for (int r = 0; r < 4; r++) {
        int hh = hi_ + r * 16;
        float4 v4 = *reinterpret_cast<const float4*>(src + (size_t)hh * LL + li4);
        t[hh][li4]     = v4.x;
        t[hh][li4 + 1] = v4.y;
        t[hh][li4 + 2] = v4.z;
        t[hh][li4 + 3] = v4.w;
    }
    __syncthreads();

    unsigned* dh = reinterpret_cast<unsigned*>(g_vth + ((size_t)(b * LL + l0)) * HH + h0);
    unsigned* dl = reinterpret_cast<unsigned*>(g_vtl + ((size_t)(b * LL + l0)) * HH + h0);
#pragma unroll
    for (int u = 0; u < 8; u++) {
        int idx = tid + u * 256;
        int li = idx >> 5;
        int h2 = idx & 31;
        float x0 = t[2 * h2][li];
        float x1 = t[2 * h2 + 1][li];
        __nv_bfloat16 h0b = __float2bfloat16(x0);
        __nv_bfloat16 h1b = __float2bfloat16(x1);
        __nv_bfloat16 l0b = __float2bfloat16(x0 - __bfloat162float(h0b));
        __nv_bfloat16 l1b = __float2bfloat16(x1 - __bfloat162float(h1b));
        unsigned ph = (unsigned)__bfloat16_as_ushort(h0b) |
                      ((unsigned)__bfloat16_as_ushort(h1b) << 16);
        unsigned pl = (unsigned)__bfloat16_as_ushort(l0b) |
                      ((unsigned)__bfloat16_as_ushort(l1b) << 16);
        dh[(size_t)li * (HH / 2) + h2] = ph;
        dl[(size_t)li * (HH / 2) + h2] = pl;
    }
}

// ============================================================
// Kernel 5: mma.sync bf16-split GEMM, retiled.
// C[b,o,l] = sum_h W[o,h] v[b,h,l] + bias[o]
// CTA 128(o) x 256(l), 8 warps (2m x 4n), warp tile 64x64.
// K = 3 segments x 1024, chunks of 32, 4-stage cp.async, 1 sync/iter.
// ============================================================
#define NCH     96
#define GSTAGES 4
#define ROWB    80                        // padded row stride (bytes) for 64B data
#define A_SZ    (128 * ROWB)              // 10240
#define B_SZ    (256 * ROWB)              // 20480
#define STG_SZ  (A_SZ + B_SZ)             // 30720
static constexpr unsigned GEMM_SMEM = GSTAGES * STG_SZ;   // 122880

__device__ __forceinline__ void gemm_load_chunk(
    uint32_t sbase, int stage, int chunk, int o0, int b, int l0, int tid)
{
    int seg = chunk >> 5;                 // 0,1,2
    int h0  = (chunk & 31) * 32;
    const __nv_bfloat16* Aseg = (seg == 1) ? g_Wl : g_Wh;
    const __nv_bfloat16* Bseg = (seg == 2) ? g_vtl : g_vth;

    uint32_t a_s = sbase + stage * STG_SZ;
    uint32_t b_s = a_s + A_SZ;

#pragma unroll
    for (int u = 0; u < 2; u++) {
        int idx = tid + u * 256;          // 0..511
        int row = idx >> 2, c = idx & 3;
        const char* g = reinterpret_cast<const char*>(
            Aseg + (size_t)(o0 + row) * HH + h0) + c * 16;
        cp_async16(a_s + row * ROWB + c * 16, g);
    }
#pragma unroll
    for (int u = 0; u < 4; u++) {
        int idx = tid + u * 256;          // 0..1023
        int row = idx >> 2, c = idx & 3;
        const char* g = reinterpret_cast<const char*>(
            Bseg + ((size_t)(b * LL + l0 + row)) * HH + h0) + c * 16;
        cp_async16(b_s + row * ROWB + c * 16, g);
    }
    cp_commit();
}

__global__ void __launch_bounds__(256) mma_gemm_kernel(
    const float* __restrict__ bias, float* __restrict__ out)
{
    extern __shared__ __align__(128) char smem[];
    uint32_t sbase = smem_u32(smem);
    int tid  = threadIdx.x;
    int wid  = tid >> 5, lane = tid & 31;
    int o0 = blockIdx.x * 128;            // o-tiles fastest -> B tile shared in L2
    int l0 = blockIdx.y * 256;
    int b  = blockIdx.z;

    int wm = wid & 1;                     // m offset 64*wm
    int wn = wid >> 1;                    // n offset 64*wn

    int a_row = ((lane >> 3) & 1) * 8 + (lane & 7);
    int a_cb  = (lane >> 4) * 16;
    int b_row = (lane >> 4) * 8 + (lane & 7);
    int b_cb  = ((lane >> 3) & 1) * 16;

    float acc[4][8][4];
#pragma unroll
    for (int mi = 0; mi < 4; mi++)
#pragma unroll
        for (int ni = 0; ni < 8; ni++)
#pragma unroll
            for (int r = 0; r < 4; r++) acc[mi][ni][r] = 0.0f;

    // prologue: stages 0..2
    gemm_load_chunk(sbase, 0, 0, o0, b, l0, tid);
    gemm_load_chunk(sbase, 1, 1, o0, b, l0, tid);
    gemm_load_chunk(sbase, 2, 2, o0, b, l0, tid);

    for (int i = 0; i < NCH; i++) {
        if (i < NCH - 3) { cp_wait<2>(); } else { cp_wait<0>(); }
        __syncthreads();

        if (i + 3 < NCH)
            gemm_load_chunk(sbase, (i + 3) & 3, i + 3, o0, b, l0, tid);

        uint32_t a_s = sbase + (i & 3) * STG_SZ;
        uint32_t b_s = a_s + A_SZ;

#pragma unroll
        for (int ks = 0; ks < 2; ks++) {
            uint32_t afrag[4][4];
#pragma unroll
            for (int mi = 0; mi < 4; mi++) {
                uint32_t addr = a_s + (wm * 64 + mi * 16 + a_row) * ROWB
                              + a_cb + ks * 32;
                ldmx4(afrag[mi][0], afrag[mi][1], afrag[mi][2], afrag[mi][3], addr);
            }
            uint32_t bfrag[4][4];
#pragma unroll
            for (int n2 = 0; n2 < 4; n2++) {
                uint32_t addr = b_s + (wn * 64 + n2 * 16 + b_row) * ROWB
                              + b_cb + ks * 32;
                ldmx4(bfrag[n2][0], bfrag[n2][1], bfrag[n2][2], bfrag[n2][3], addr);
            }
#pragma unroll
            for (int mi = 0; mi < 4; mi++)
#pragma unroll
                for (int ni = 0; ni < 8; ni++)
                    mma16816(acc[mi][ni], afrag[mi],
                             bfrag[ni >> 1][(ni & 1) * 2],
                             bfrag[ni >> 1][(ni & 1) * 2 + 1]);
        }
    }
    __syncthreads();

    // epilogue
#pragma unroll
    for (int mi = 0; mi < 4; mi++) {
        int o_a = o0 + wm * 64 + mi * 16 + (lane >> 2);
        int o_b = o_a + 8;
        float bo_a = __ldg(bias + o_a);
        float bo_b = __ldg(bias + o_b);
#pragma unroll
        for (int ni = 0; ni < 8; ni++) {
            int l = l0 + wn * 64 + ni * 8 + (lane & 3) * 2;
            float2 v0 = make_float2(acc[mi][ni][0] + bo_a, acc[mi][ni][1] + bo_a);
            float2 v1 = make_float2(acc[mi][ni][2] + bo_b, acc[mi][ni][3] + bo_b);
            *reinterpret_cast<float2*>(out + ((size_t)(b * HH + o_a)) * LL + l) = v0;
            *reinterpret_cast<float2*>(out + ((size_t)(b * HH + o_b)) * LL + l) = v1;
        }
    }
}

// ============================================================
extern "C" void kernel_launch(void* const* d_in, const int* in_sizes, int n_in,
                              void* d_out, int out_size)
{
    (void)in_sizes; (void)n_in; (void)out_size;
    const float* u    = (const float*)d_in[0];
    const float* k0   = (const float*)d_in[1];
    const float* k1   = (const float*)d_in[2];
    const float* k2   = (const float*)d_in[3];
    const float* k3   = (const float*)d_in[4];
    const float* D    = (const float*)d_in[5];
    const float* W    = (const float*)d_in[6];
    const float* bias = (const float*)d_in[7];
    float* out = (float*)d_out;

    cudaFuncSetAttribute(mma_gemm_kernel,
                         cudaFuncAttributeMaxDynamicSharedMemorySize, GEMM_SMEM);

    build_k_kernel<<<HH, 128>>>(k0, k1, k2, k3);
    conv_gelu_kernel<<<dim3(LL / CTILE, BB * HH), 256>>>(u, D);
    wconv_kernel<<<(HH * HH) / 1024, 256>>>(W);
    transpose_convert_kernel<<<dim3(LL / 64, HH / 64, BB), 256>>>();
    mma_gemm_kernel<<<dim3(HH / 128, LL / 256, BB), 256, GEMM_SMEM>>>(bias, out);
}

// round 9
// speedup vs baseline: 1.3109x; 1.3109x over previous
#include <cuda_runtime.h>
#include <cuda_bf16.h>
#include <cuda_fp16.h>
#include <cstdint>
#include <math.h>

// Problem constants
#define BB   4
#define HH   1024
#define LL   8192
#define KD   64
#define KLEN 512      // KD * 2^(NS-1)

// ---------------- static device scratch ----------------
__device__ float g_k[HH * KLEN];                         // normalized kernel [h][t]
__device__ float g_v[(size_t)BB * HH * LL];              // gelu(conv + u*D) [b][h][l]  (128 MB)
__device__ __half g_vt[(size_t)BB * LL * HH];            // v transposed fp16 [b][l][h]  (64 MB)
__device__ __half g_Wf[HH * HH];                         // W fp16 [o][h]

// ---------------- f32x2 packed helpers ----------------
__device__ __forceinline__ unsigned long long pk2(float a, float b) {
    unsigned long long r;
    asm("mov.b64 %0, {%1, %2};" : "=l"(r) : "f"(a), "f"(b));
    return r;
}
__device__ __forceinline__ void upk2(unsigned long long v, float& a, float& b) {
    asm("mov.b64 {%0, %1}, %2;" : "=f"(a), "=f"(b) : "l"(v));
}
__device__ __forceinline__ void fma2(unsigned long long& d, unsigned long long a,
                                     unsigned long long b) {
    asm("fma.rn.f32x2 %0, %1, %2, %0;" : "+l"(d) : "l"(a), "l"(b));
}

// ---------------- PTX helpers (baseline ISA only) ----------------
__device__ __forceinline__ uint32_t smem_u32(const void* p) {
    uint32_t a;
    asm("{ .reg .u64 t; cvta.to.shared.u64 t, %1; cvt.u32.u64 %0, t; }" : "=r"(a) : "l"(p));
    return a;
}
__device__ __forceinline__ void cp_async16(uint32_t sa, const void* g) {
    asm volatile("cp.async.cg.shared.global [%0], [%1], 16;" :: "r"(sa), "l"(g));
}
__device__ __forceinline__ void cp_commit() {
    asm volatile("cp.async.commit_group;" ::: "memory");
}
template<int N> __device__ __forceinline__ void cp_wait() {
    asm volatile("cp.async.wait_group %0;" :: "n"(N) : "memory");
}
__device__ __forceinline__ void ldmx4(uint32_t& r0, uint32_t& r1, uint32_t& r2, uint32_t& r3,
                                      uint32_t addr) {
    asm volatile("ldmatrix.sync.aligned.m8n8.x4.shared.b16 {%0,%1,%2,%3}, [%4];"
                 : "=r"(r0), "=r"(r1), "=r"(r2), "=r"(r3) : "r"(addr));
}
__device__ __forceinline__ void mma16816h(float* c, const uint32_t* a, uint32_t b0, uint32_t b1) {
    asm volatile(
        "mma.sync.aligned.m16n8k16.row.col.f32.f16.f16.f32 "
        "{%0,%1,%2,%3}, {%4,%5,%6,%7}, {%8,%9}, {%0,%1,%2,%3};"
        : "+f"(c[0]), "+f"(c[1]), "+f"(c[2]), "+f"(c[3])
        : "r"(a[0]), "r"(a[1]), "r"(a[2]), "r"(a[3]), "r"(b0), "r"(b1));
}

// ============================================================
// Kernel 1: build combined, normalized conv kernel per head.
// ============================================================
__global__ void __launch_bounds__(128) build_k_kernel(
    const float* __restrict__ k0, const float* __restrict__ k1,
    const float* __restrict__ k2, const float* __restrict__ k3)
{
    int h   = blockIdx.x;
    int tid = threadIdx.x;
    const float* ks[4] = { k0 + h * KD, k1 + h * KD, k2 + h * KD, k3 + h * KD };

    float vals[4];
    float ss = 0.0f;
#pragma unroll
    for (int r = 0; r < 4; r++) {
        int t = tid + r * 128;
        float acc = 0.0f;
#pragma unroll
        for (int i = 0; i < 4; i++) {
            int len = KD << i;
            if (t < len) {
                float s = (float)(1 << i);
                float coord = (t + 0.5f) / s - 0.5f;
                coord = fminf(fmaxf(coord, 0.0f), 63.0f);
                int lo  = (int)floorf(coord);
                float w = coord - (float)lo;
                int hi  = min(lo + 1, 63);
                float val = ks[i][lo] * (1.0f - w) + ks[i][hi] * w;
                acc += val * (float)(1 << (3 - i));
            }
        }
        vals[r] = acc;
        ss += acc * acc;
    }

    __shared__ float red[128];
    red[tid] = ss;
    __syncthreads();
    for (int s = 64; s > 0; s >>= 1) {
        if (tid < s) red[tid] += red[tid + s];
        __syncthreads();
    }
    float inv = 1.0f / sqrtf(red[0]);
#pragma unroll
    for (int r = 0; r < 4; r++)
        g_k[h * KLEN + tid + r * 128] = vals[r] * inv;
}

// ============================================================
// Kernel 2: causal 512-tap conv + u*D + exact GELU -> g_v  (proven)
// ============================================================
#define CTILE 2048

__global__ void __launch_bounds__(256) conv_gelu_kernel(
    const float* __restrict__ u, const float* __restrict__ D)
{
    int bh  = blockIdx.y;
    int h   = bh & (HH - 1);
    int l0  = blockIdx.x * CTILE;
    int tid = threadIdx.x;

    __shared__ float k_s[KLEN];
    __shared__ float u_s[KLEN + CTILE];

    const float* ub = u + (size_t)bh * LL;

#pragma unroll
    for (int i = 0; i < 2; i++)
        k_s[tid + i * 256] = g_k[h * KLEN + tid + i * 256];
#pragma unroll
    for (int i = 0; i < 10; i++) {
        int idx = tid + i * 256;
        int g = l0 - KLEN + idx;
        u_s[idx] = (g >= 0) ? ub[g] : 0.0f;
    }
    __syncthreads();

    int li = tid * 8;
    const float* up = u_s + KLEN + li;

    unsigned long long acc2[4];
#pragma unroll
    for (int p = 0; p < 4; p++) acc2[p] = 0ull;

#pragma unroll 2
    for (int t = 0; t < KLEN; t += 4) {
        float4 k4 = *reinterpret_cast<const float4*>(k_s + t);
        float uv[12];
        *reinterpret_cast<float4*>(uv)     = *reinterpret_cast<const float4*>(up - t - 4);
        *reinterpret_cast<float4*>(uv + 4) = *reinterpret_cast<const float4*>(up - t);
        *reinterpret_cast<float4*>(uv + 8) = *reinterpret_cast<const float4*>(up - t + 4);
        const unsigned long long* uvl = reinterpret_cast<const unsigned long long*>(uv);

        unsigned long long kp0 = pk2(k4.x, k4.x);
        unsigned long long kp1 = pk2(k4.y, k4.y);
        unsigned long long kp2 = pk2(k4.z, k4.z);
        unsigned long long kp3 = pk2(k4.w, k4.w);
        unsigned long long po[5];
#pragma unroll
        for (int q = 0; q < 5; q++) po[q] = pk2(uv[2 * q + 1], uv[2 * q + 2]);

#pragma unroll
        for (int p = 0; p < 4; p++) {
            fma2(acc2[p], kp0, uvl[p + 2]);
            fma2(acc2[p], kp1, po[p + 1]);
            fma2(acc2[p], kp2, uvl[p + 1]);
            fma2(acc2[p], kp3, po[p]);
        }
    }

    float res[8];
#pragma unroll
    for (int p = 0; p < 4; p++) upk2(acc2[p], res[2 * p], res[2 * p + 1]);

    float d = D[h];
    float4 uc0 = *reinterpret_cast<const float4*>(up);
    float4 uc1 = *reinterpret_cast<const float4*>(up + 4);
    float uu[8] = { uc0.x, uc0.y, uc0.z, uc0.w, uc1.x, uc1.y, uc1.z, uc1.w };

    float outv[8];
#pragma unroll
    for (int r = 0; r < 8; r++) {
        float x = res[r] + uu[r] * d;
        outv[r] = 0.5f * x * (1.0f + erff(x * 0.70710678118654752f));
    }

    float* vb = g_v + (size_t)bh * LL + l0 + li;
    *reinterpret_cast<float4*>(vb)     = make_float4(outv[0], outv[1], outv[2], outv[3]);
    *reinterpret_cast<float4*>(vb + 4) = make_float4(outv[4], outv[5], outv[6], outv[7]);
}

// ============================================================
// Kernel 3: W f32 -> fp16 (same layout [o][h])
// ============================================================
__global__ void __launch_bounds__(256) wconv_kernel(const float* __restrict__ W)
{
    int base = (blockIdx.x * 256 + threadIdx.x) * 4;
#pragma unroll
    for (int i = 0; i < 4; i++)
        g_Wf[base + i] = __float2half(W[base + i]);
}

// ============================================================
// Kernel 4: transpose + convert v[b][h][l] f32 -> fp16 [b][l][h]
// ============================================================
__global__ void __launch_bounds__(256) transpose_convert_kernel()
{
    int b  = blockIdx.z;
    int h0 = blockIdx.y * 64;
    int l0 = blockIdx.x * 64;
    int tid = threadIdx.x;

    __shared__ float t[64][65];

    int hi_ = tid >> 4;
    int li4 = (tid & 15) * 4;
    const float* src = g_v + ((size_t)(b * HH + h0)) * LL + l0;
#pragma unroll
    for (int r = 0; r < 4; r++) {
        int hh = hi_ + r * 16;
        float4 v4 = *reinterpret_cast<const float4*>(src + (size_t)hh * LL + li4);
        t[hh][li4]     = v4.x;
        t[hh][li4 + 1] = v4.y;
        t[hh][li4 + 2] = v4.z;
        t[hh][li4 + 3] = v4.w;
    }
    __syncthreads();

    unsigned* dh = reinterpret_cast<unsigned*>(g_vt + ((size_t)(b * LL + l0)) * HH + h0);
#pragma unroll
    for (int u = 0; u < 8; u++) {
        int idx = tid + u * 256;
        int li = idx >> 5;
        int h2 = idx & 31;
        __half2 p = __floats2half2_rn(t[2 * h2][li], t[2 * h2 + 1][li]);
        dh[(size_t)li * (HH / 2) + h2] = *reinterpret_cast<unsigned*>(&p);
    }
}

// ============================================================
// Kernel 5: mma.sync fp16 GEMM (single segment, K=1024).
// C[b,o,l] = sum_h W[o,h] v[b,h,l] + bias[o]
// CTA 128(o) x 256(l), 8 warps (2m x 4n), warp tile 64x64.
// K chunks of 32, 4-stage cp.async, 1 sync/iter.
// ============================================================
#define NCH     32
#define GSTAGES 4
#define ROWB    80                        // padded row stride (bytes) for 64B data
#define A_SZ    (128 * ROWB)              // 10240
#define B_SZ    (256 * ROWB)              // 20480
#define STG_SZ  (A_SZ + B_SZ)             // 30720
static constexpr unsigned GEMM_SMEM = GSTAGES * STG_SZ;   // 122880

__device__ __forceinline__ void gemm_load_chunk(
    uint32_t sbase, int stage, int chunk, int o0, int b, int l0, int tid)
{
    int h0 = chunk * 32;
    uint32_t a_s = sbase + stage * STG_SZ;
    uint32_t b_s = a_s + A_SZ;

#pragma unroll
    for (int u = 0; u < 2; u++) {
        int idx = tid + u * 256;          // 0..511
        int row = idx >> 2, c = idx & 3;
        const char* g = reinterpret_cast<const char*>(
            g_Wf + (size_t)(o0 + row) * HH + h0) + c * 16;
        cp_async16(a_s + row * ROWB + c * 16, g);
    }
#pragma unroll
    for (int u = 0; u < 4; u++) {
        int idx = tid + u * 256;          // 0..1023
        int row = idx >> 2, c = idx & 3;
        const char* g = reinterpret_cast<const char*>(
            g_vt + ((size_t)(b * LL + l0 + row)) * HH + h0) + c * 16;
        cp_async16(b_s + row * ROWB + c * 16, g);
    }
    cp_commit();
}

__global__ void __launch_bounds__(256) mma_gemm_kernel(
    const float* __restrict__ bias, float* __restrict__ out)
{
    extern __shared__ __align__(128) char smem[];
    uint32_t sbase = smem_u32(smem);
    int tid  = threadIdx.x;
    int wid  = tid >> 5, lane = tid & 31;
    int o0 = blockIdx.x * 128;            // o-tiles fastest -> B tile shared in L2
    int l0 = blockIdx.y * 256;
    int b  = blockIdx.z;

    int wm = wid & 1;                     // m offset 64*wm
    int wn = wid >> 1;                    // n offset 64*wn

    int a_row = ((lane >> 3) & 1) * 8 + (lane & 7);
    int a_cb  = (lane >> 4) * 16;
    int b_row = (lane >> 4) * 8 + (lane & 7);
    int b_cb  = ((lane >> 3) & 1) * 16;

    float acc[4][8][4];
#pragma unroll
    for (int mi = 0; mi < 4; mi++)
#pragma unroll
        for (int ni = 0; ni < 8; ni++)
#pragma unroll
            for (int r = 0; r < 4; r++) acc[mi][ni][r] = 0.0f;

    // prologue: stages 0..2
    gemm_load_chunk(sbase, 0, 0, o0, b, l0, tid);
    gemm_load_chunk(sbase, 1, 1, o0, b, l0, tid);
    gemm_load_chunk(sbase, 2, 2, o0, b, l0, tid);

    for (int i = 0; i < NCH; i++) {
        if (i < NCH - 3) { cp_wait<2>(); } else { cp_wait<0>(); }
        __syncthreads();

        if (i + 3 < NCH)
            gemm_load_chunk(sbase, (i + 3) & 3, i + 3, o0, b, l0, tid);

        uint32_t a_s = sbase + (i & 3) * STG_SZ;
        uint32_t b_s = a_s + A_SZ;

#pragma unroll
        for (int ks = 0; ks < 2; ks++) {
            uint32_t afrag[4][4];
#pragma unroll
            for (int mi = 0; mi < 4; mi++) {
                uint32_t addr = a_s + (wm * 64 + mi * 16 + a_row) * ROWB
                              + a_cb + ks * 32;
                ldmx4(afrag[mi][0], afrag[mi][1], afrag[mi][2], afrag[mi][3], addr);
            }
            uint32_t bfrag[4][4];
#pragma unroll
            for (int n2 = 0; n2 < 4; n2++) {
                uint32_t addr = b_s + (wn * 64 + n2 * 16 + b_row) * ROWB
                              + b_cb + ks * 32;
                ldmx4(bfrag[n2][0], bfrag[n2][1], bfrag[n2][2], bfrag[n2][3], addr);
            }
#pragma unroll
            for (int mi = 0; mi < 4; mi++)
#pragma unroll
                for (int ni = 0; ni < 8; ni++)
                    mma16816h(acc[mi][ni], afrag[mi],
                              bfrag[ni >> 1][(ni & 1) * 2],
                              bfrag[ni >> 1][(ni & 1) * 2 + 1]);
        }
    }
    __syncthreads();

    // epilogue
#pragma unroll
    for (int mi = 0; mi < 4; mi++) {
        int o_a = o0 + wm * 64 + mi * 16 + (lane >> 2);
        int o_b = o_a + 8;
        float bo_a = __ldg(bias + o_a);
        float bo_b = __ldg(bias + o_b);
#pragma unroll
        for (int ni = 0; ni < 8; ni++) {
            int l = l0 + wn * 64 + ni * 8 + (lane & 3) * 2;
            float2 v0 = make_float2(acc[mi][ni][0] + bo_a, acc[mi][ni][1] + bo_a);
            float2 v1 = make_float2(acc[mi][ni][2] + bo_b, acc[mi][ni][3] + bo_b);
            *reinterpret_cast<float2*>(out + ((size_t)(b * HH + o_a)) * LL + l) = v0;
            *reinterpret_cast<float2*>(out + ((size_t)(b * HH + o_b)) * LL + l) = v1;
        }
    }
}

// ============================================================
extern "C" void kernel_launch(void* const* d_in, const int* in_sizes, int n_in,
                              void* d_out, int out_size)
{
    (void)in_sizes; (void)n_in; (void)out_size;
    const float* u    = (const float*)d_in[0];
    const float* k0   = (const float*)d_in[1];
    const float* k1   = (const float*)d_in[2];
    const float* k2   = (const float*)d_in[3];
    const float* k3   = (const float*)d_in[4];
    const float* D    = (const float*)d_in[5];
    const float* W    = (const float*)d_in[6];
    const float* bias = (const float*)d_in[7];
    float* out = (float*)d_out;

    cudaFuncSetAttribute(mma_gemm_kernel,
                         cudaFuncAttributeMaxDynamicSharedMemorySize, GEMM_SMEM);

    build_k_kernel<<<HH, 128>>>(k0, k1, k2, k3);
    conv_gelu_kernel<<<dim3(LL / CTILE, BB * HH), 256>>>(u, D);
    wconv_kernel<<<(HH * HH) / 1024, 256>>>(W);
    transpose_convert_kernel<<<dim3(LL / 64, HH / 64, BB), 256>>>();
    mma_gemm_kernel<<<dim3(HH / 128, LL / 256, BB), 256, GEMM_SMEM>>>(bias, out);
}

// round 11
// speedup vs baseline: 3.8364x; 2.9265x over previous
#include <cuda_runtime.h>
#include <cuda_bf16.h>
#include <cuda_fp16.h>
#include <cstdint>
#include <math.h>

// Problem constants
#define BB   4
#define HH   1024
#define LL   8192
#define KD   64
#define KLEN 512      // KD * 2^(NS-1)

// ---------------- static device scratch ----------------
__device__ float g_k[HH * KLEN];                         // normalized kernel [h][t]
__device__ float g_v[(size_t)BB * HH * LL];              // gelu(conv + u*D) [b][h][l]  (128 MB)
__device__ __half g_vt[(size_t)BB * LL * HH];            // v transposed fp16 [b][l][h]  (64 MB)
__device__ __half g_Wf[HH * HH];                         // W fp16 [o][h]

// ---------------- PTX helpers (baseline ISA only) ----------------
__device__ __forceinline__ uint32_t smem_u32(const void* p) {
    uint32_t a;
    asm("{ .reg .u64 t; cvta.to.shared.u64 t, %1; cvt.u32.u64 %0, t; }" : "=r"(a) : "l"(p));
    return a;
}
__device__ __forceinline__ void cp_async16(uint32_t sa, const void* g) {
    asm volatile("cp.async.cg.shared.global [%0], [%1], 16;" :: "r"(sa), "l"(g));
}
__device__ __forceinline__ void cp_commit() {
    asm volatile("cp.async.commit_group;" ::: "memory");
}
template<int N> __device__ __forceinline__ void cp_wait() {
    asm volatile("cp.async.wait_group %0;" :: "n"(N) : "memory");
}
__device__ __forceinline__ void ldmx4(uint32_t& r0, uint32_t& r1, uint32_t& r2, uint32_t& r3,
                                      uint32_t addr) {
    asm volatile("ldmatrix.sync.aligned.m8n8.x4.shared.b16 {%0,%1,%2,%3}, [%4];"
                 : "=r"(r0), "=r"(r1), "=r"(r2), "=r"(r3) : "r"(addr));
}
__device__ __forceinline__ void mma16816h(float* c, const uint32_t* a, uint32_t b0, uint32_t b1) {
    asm volatile(
        "mma.sync.aligned.m16n8k16.row.col.f32.f16.f16.f32 "
        "{%0,%1,%2,%3}, {%4,%5,%6,%7}, {%8,%9}, {%0,%1,%2,%3};"
        : "+f"(c[0]), "+f"(c[1]), "+f"(c[2]), "+f"(c[3])
        : "r"(a[0]), "r"(a[1]), "r"(a[2]), "r"(a[3]), "r"(b0), "r"(b1));
}

// ============================================================
// Kernel 1: build combined, normalized conv kernel per head.
// ============================================================
__global__ void __launch_bounds__(128) build_k_kernel(
    const float* __restrict__ k0, const float* __restrict__ k1,
    const float* __restrict__ k2, const float* __restrict__ k3)
{
    int h   = blockIdx.x;
    int tid = threadIdx.x;
    const float* ks[4] = { k0 + h * KD, k1 + h * KD, k2 + h * KD, k3 + h * KD };

    float vals[4];
    float ss = 0.0f;
#pragma unroll
    for (int r = 0; r < 4; r++) {
        int t = tid + r * 128;
        float acc = 0.0f;
#pragma unroll
        for (int i = 0; i < 4; i++) {
            int len = KD << i;
            if (t < len) {
                float s = (float)(1 << i);
                float coord = (t + 0.5f) / s - 0.5f;
                coord = fminf(fmaxf(coord, 0.0f), 63.0f);
                int lo  = (int)floorf(coord);
                float w = coord - (float)lo;
                int hi  = min(lo + 1, 63);
                float val = ks[i][lo] * (1.0f - w) + ks[i][hi] * w;
                acc += val * (float)(1 << (3 - i));
            }
        }
        vals[r] = acc;
        ss += acc * acc;
    }

    __shared__ float red[128];
    red[tid] = ss;
    __syncthreads();
    for (int s = 64; s > 0; s >>= 1) {
        if (tid < s) red[tid] += red[tid + s];
        __syncthreads();
    }
    float inv = 1.0f / sqrtf(red[0]);
#pragma unroll
    for (int r = 0; r < 4; r++)
        g_k[h * KLEN + tid + r * 128] = vals[r] * inv;
}

// ============================================================
// Kernel 2: block-Toeplitz tensor-core conv + u*D + exact GELU -> g_v
// One CTA per (b,h). y_m = sum_{d=0}^{32} K_d u_{m-d},
// K_d[i][j] = k[16d+i-j].  A = K_d (smem Toeplitz table),
// B = fp16 u windows at shifted ldmatrix addresses.
// 8 warps, warp w owns m-blocks [64w, 64w+64) = 4 tiles of N=16.
// ============================================================
#define SM_U16  0                         // 17408 halves (512 zero pad + 8192)
#define SM_U32  34816                     // 8192 f32
#define SM_A    67584                     // 33 * 768 B (16 rows x 48B pitch)
#define SM_K    92928                     // 512 f32
#define SM_STG  94976                     // 8 warps * 1088 B
#define CONV_SMEM 103680

__global__ void __launch_bounds__(256) conv_mma_kernel(
    const float* __restrict__ u, const float* __restrict__ D)
{
    extern __shared__ __align__(128) char smem[];
    uint32_t sbase = smem_u32(smem);
    __half* u16 = reinterpret_cast<__half*>(smem + SM_U16);
    float*  u32 = reinterpret_cast<float*>(smem + SM_U32);
    __half* Atb = reinterpret_cast<__half*>(smem + SM_A);
    float*  kf  = reinterpret_cast<float*>(smem + SM_K);

    int bh  = blockIdx.x;
    int h   = bh & (HH - 1);
    int tid = threadIdx.x;
    int wid = tid >> 5, lane = tid & 31;

    // ---- load u row: fp32 copy + fp16 copy (with 512-half zero prefix) ----
    const float* ub = u + (size_t)bh * LL;
    if (tid < 128) {                      // zero pad: 512 halves
        uint2 z = make_uint2(0u, 0u);
        *reinterpret_cast<uint2*>(u16 + tid * 4) = z;
    }
#pragma unroll 4
    for (int i = tid; i < LL / 4; i += 256) {
        float4 v4 = *reinterpret_cast<const float4*>(ub + i * 4);
        *reinterpret_cast<float4*>(u32 + i * 4) = v4;
        __half2 p0 = __floats2half2_rn(v4.x, v4.y);
        __half2 p1 = __floats2half2_rn(v4.z, v4.w);
        uint2 pk;
        pk.x = *reinterpret_cast<unsigned*>(&p0);
        pk.y = *reinterpret_cast<unsigned*>(&p1);
        *reinterpret_cast<uint2*>(u16 + KLEN + i * 4) = pk;
    }
    // ---- load k row fp32 ----
    kf[tid]       = g_k[h * KLEN + tid];
    kf[tid + 256] = g_k[h * KLEN + tid + 256];
    __syncthreads();

    // ---- build Toeplitz table: Atb[d][i][j] = k[16d+i-j] ----
    {
        int i_ = tid >> 4, j_ = tid & 15;
#pragma unroll
        for (int d = 0; d < 33; d++) {
            int tau = d * 16 + i_ - j_;
            __half val = (tau >= 0 && tau < KLEN) ? __float2half(kf[tau]) : __half(0);
            Atb[d * 384 + i_ * 24 + j_] = val;   // 48B row pitch (24 halves)
        }
    }
    __syncthreads();

    // ---- main MMA loop ----
    int a_row = (lane & 7) + ((lane >> 3) & 1) * 8;
    int a_cb  = (lane >> 4) * 16;
    int b_nrow = (lane >> 4) * 8 + (lane & 7);
    int b_cb  = ((lane >> 3) & 1) * 16;

    uint32_t aBase = sbase + SM_A + a_row * 48 + a_cb;
    uint32_t uBase = sbase + SM_U16 + 1024 + 32 * (wid * 64 + b_nrow) + b_cb;

    float acc[4][2][4];
#pragma unroll
    for (int t = 0; t < 4; t++)
#pragma unroll
        for (int mm = 0; mm < 2; mm++)
#pragma unroll
            for (int r = 0; r < 4; r++) acc[t][mm][r] = 0.0f;

    for (int d = 0; d < 33; d++) {
        uint32_t af[4];
        ldmx4(af[0], af[1], af[2], af[3], aBase + d * 768);
        uint32_t ub0 = uBase - 32 * d;
#pragma unroll
        for (int t = 0; t < 4; t++) {
            uint32_t b0, b1, b2, b3;
            ldmx4(b0, b1, b2, b3, ub0 + t * 512);
            mma16816h(acc[t][0], af, b0, b1);
            mma16816h(acc[t][1], af, b2, b3);
        }
    }

    // ---- epilogue: stage -> +u*D -> exact GELU -> g_v (coalesced) ----
    float Dh = D[h];
    float* st = reinterpret_cast<float*>(smem + SM_STG) + wid * 272;  // 16x17 f32
    float* vb = g_v + (size_t)bh * LL;
    int ir = lane >> 2;
    int c0 = (lane & 3) * 2;

#pragma unroll
    for (int t = 0; t < 4; t++) {
#pragma unroll
        for (int mm = 0; mm < 2; mm++) {
            st[ir * 17 + mm * 8 + c0]           = acc[t][mm][0];
            st[ir * 17 + mm * 8 + c0 + 1]       = acc[t][mm][1];
            st[(ir + 8) * 17 + mm * 8 + c0]     = acc[t][mm][2];
            st[(ir + 8) * 17 + mm * 8 + c0 + 1] = acc[t][mm][3];
        }
        __syncwarp();
        int lbase = wid * 1024 + t * 256 + lane * 8;
        float o8[8];
#pragma unroll
        for (int r = 0; r < 8; r++) {
            int l_loc = lane * 8 + r;
            float y = st[(l_loc & 15) * 17 + (l_loc >> 4)];
            float x = y + u32[lbase + r] * Dh;
            o8[r] = 0.5f * x * (1.0f + erff(x * 0.70710678118654752f));
        }
        *reinterpret_cast<float4*>(vb + lbase)     = make_float4(o8[0], o8[1], o8[2], o8[3]);
        *reinterpret_cast<float4*>(vb + lbase + 4) = make_float4(o8[4], o8[5], o8[6], o8[7]);
        __syncwarp();
    }
}

// ============================================================
// Kernel 3: W f32 -> fp16 (same layout [o][h])
// ============================================================
__global__ void __launch_bounds__(256) wconv_kernel(const float* __restrict__ W)
{
    int base = (blockIdx.x * 256 + threadIdx.x) * 4;
#pragma unroll
    for (int i = 0; i < 4; i++)
        g_Wf[base + i] = __float2half(W[base + i]);
}

// ============================================================
// Kernel 4: transpose + convert v[b][h][l] f32 -> fp16 [b][l][h]
// ============================================================
__global__ void __launch_bounds__(256) transpose_convert_kernel()
{
    int b  = blockIdx.z;
    int h0 = blockIdx.y * 64;
    int l0 = blockIdx.x * 64;
    int tid = threadIdx.x;

    __shared__ float t[64][65];

    int hi_ = tid >> 4;
    int li4 = (tid & 15) * 4;
    const float* src = g_v + ((size_t)(b * HH + h0)) * LL + l0;
#pragma unroll
    for (int r = 0; r < 4; r++) {
        int hh = hi_ + r * 16;
        float4 v4 = *reinterpret_cast<const float4*>(src + (size_t)hh * LL + li4);
        t[hh][li4]     = v4.x;
        t[hh][li4 + 1] = v4.y;
        t[hh][li4 + 2] = v4.z;
        t[hh][li4 + 3] = v4.w;
    }
    __syncthreads();

    unsigned* dh = reinterpret_cast<unsigned*>(g_vt + ((size_t)(b * LL + l0)) * HH + h0);
#pragma unroll
    for (int u = 0; u < 8; u++) {
        int idx = tid + u * 256;
        int li = idx >> 5;
        int h2 = idx & 31;
        __half2 p = __floats2half2_rn(t[2 * h2][li], t[2 * h2 + 1][li]);
        dh[(size_t)li * (HH / 2) + h2] = *reinterpret_cast<unsigned*>(&p);
    }
}

// ============================================================
// Kernel 5: mma.sync fp16 GEMM (single segment, K=1024).  (proven R7)
// ============================================================
#define NCH     32
#define GSTAGES 4
#define ROWB    80
#define A_SZ    (128 * ROWB)
#define B_SZ    (256 * ROWB)
#define STG_SZ  (A_SZ + B_SZ)
static constexpr unsigned GEMM_SMEM = GSTAGES * STG_SZ;   // 122880

__device__ __forceinline__ void gemm_load_chunk(
    uint32_t sbase, int stage, int chunk, int o0, int b, int l0, int tid)
{
    int h0 = chunk * 32;
    uint32_t a_s = sbase + stage * STG_SZ;
    uint32_t b_s = a_s + A_SZ;

#pragma unroll
    for (int u = 0; u < 2; u++) {
        int idx = tid + u * 256;
        int row = idx >> 2, c = idx & 3;
        const char* g = reinterpret_cast<const char*>(
            g_Wf + (size_t)(o0 + row) * HH + h0) + c * 16;
        cp_async16(a_s + row * ROWB + c * 16, g);
    }
#pragma unroll
    for (int u = 0; u < 4; u++) {
        int idx = tid + u * 256;
        int row = idx >> 2, c = idx & 3;
        const char* g = reinterpret_cast<const char*>(
            g_vt + ((size_t)(b * LL + l0 + row)) * HH + h0) + c * 16;
        cp_async16(b_s + row * ROWB + c * 16, g);
    }
    cp_commit();
}

__global__ void __launch_bounds__(256) mma_gemm_kernel(
    const float* __restrict__ bias, float* __restrict__ out)
{
    extern __shared__ __align__(128) char smem[];
    uint32_t sbase = smem_u32(smem);
    int tid  = threadIdx.x;
    int wid  = tid >> 5, lane = tid & 31;
    int o0 = blockIdx.x * 128;
    int l0 = blockIdx.y * 256;
    int b  = blockIdx.z;

    int wm = wid & 1;
    int wn = wid >> 1;

    int a_row = ((lane >> 3) & 1) * 8 + (lane & 7);
    int a_cb  = (lane >> 4) * 16;
    int b_row = (lane >> 4) * 8 + (lane & 7);
    int b_cb  = ((lane >> 3) & 1) * 16;

    float acc[4][8][4];
#pragma unroll
    for (int mi = 0; mi < 4; mi++)
#pragma unroll
        for (int ni = 0; ni < 8; ni++)
#pragma unroll
            for (int r = 0; r < 4; r++) acc[mi][ni][r] = 0.0f;

    gemm_load_chunk(sbase, 0, 0, o0, b, l0, tid);
    gemm_load_chunk(sbase, 1, 1, o0, b, l0, tid);
    gemm_load_chunk(sbase, 2, 2, o0, b, l0, tid);

    for (int i = 0; i < NCH; i++) {
        if (i < NCH - 3) { cp_wait<2>(); } else { cp_wait<0>(); }
        __syncthreads();

        if (i + 3 < NCH)
            gemm_load_chunk(sbase, (i + 3) & 3, i + 3, o0, b, l0, tid);

        uint32_t a_s = sbase + (i & 3) * STG_SZ;
        uint32_t b_s = a_s + A_SZ;

#pragma unroll
        for (int ks = 0; ks < 2; ks++) {
            uint32_t afrag[4][4];
#pragma unroll
            for (int mi = 0; mi < 4; mi++) {
                uint32_t addr = a_s + (wm * 64 + mi * 16 + a_row) * ROWB
                              + a_cb + ks * 32;
                ldmx4(afrag[mi][0], afrag[mi][1], afrag[mi][2], afrag[mi][3], addr);
            }
            uint32_t bfrag[4][4];
#pragma unroll
            for (int n2 = 0; n2 < 4; n2++) {
                uint32_t addr = b_s + (wn * 64 + n2 * 16 + b_row) * ROWB
                              + b_cb + ks * 32;
                ldmx4(bfrag[n2][0], bfrag[n2][1], bfrag[n2][2], bfrag[n2][3], addr);
            }
#pragma unroll
            for (int mi = 0; mi < 4; mi++)
#pragma unroll
                for (int ni = 0; ni < 8; ni++)
                    mma16816h(acc[mi][ni], afrag[mi],
                              bfrag[ni >> 1][(ni & 1) * 2],
                              bfrag[ni >> 1][(ni & 1) * 2 + 1]);
        }
    }
    __syncthreads();

#pragma unroll
    for (int mi = 0; mi < 4; mi++) {
        int o_a = o0 + wm * 64 + mi * 16 + (lane >> 2);
        int o_b = o_a + 8;
        float bo_a = __ldg(bias + o_a);
        float bo_b = __ldg(bias + o_b);
#pragma unroll
        for (int ni = 0; ni < 8; ni++) {
            int l = l0 + wn * 64 + ni * 8 + (lane & 3) * 2;
            float2 v0 = make_float2(acc[mi][ni][0] + bo_a, acc[mi][ni][1] + bo_a);
            float2 v1 = make_float2(acc[mi][ni][2] + bo_b, acc[mi][ni][3] + bo_b);
            *reinterpret_cast<float2*>(out + ((size_t)(b * HH + o_a)) * LL + l) = v0;
            *reinterpret_cast<float2*>(out + ((size_t)(b * HH + o_b)) * LL + l) = v1;
        }
    }
}

// ============================================================
extern "C" void kernel_launch(void* const* d_in, const int* in_sizes, int n_in,
                              void* d_out, int out_size)
{
    (void)in_sizes; (void)n_in; (void)out_size;
    const float* u    = (const float*)d_in[0];
    const float* k0   = (const float*)d_in[1];
    const float* k1   = (const float*)d_in[2];
    const float* k2   = (const float*)d_in[3];
    const float* k3   = (const float*)d_in[4];
    const float* D    = (const float*)d_in[5];
    const float* W    = (const float*)d_in[6];
    const float* bias = (const float*)d_in[7];
    float* out = (float*)d_out;

    cudaFuncSetAttribute(mma_gemm_kernel,
                         cudaFuncAttributeMaxDynamicSharedMemorySize, GEMM_SMEM);
    cudaFuncSetAttribute(conv_mma_kernel,
                         cudaFuncAttributeMaxDynamicSharedMemorySize, CONV_SMEM);

    build_k_kernel<<<HH, 128>>>(k0, k1, k2, k3);
    conv_mma_kernel<<<BB * HH, 256, CONV_SMEM>>>(u, D);
    wconv_kernel<<<(HH * HH) / 1024, 256>>>(W);
    transpose_convert_kernel<<<dim3(LL / 64, HH / 64, BB), 256>>>();
    mma_gemm_kernel<<<dim3(HH / 128, LL / 256, BB), 256, GEMM_SMEM>>>(bias, out);
}

// round 12
// speedup vs baseline: 4.2770x; 1.1148x over previous
#include <cuda_runtime.h>
#include <cuda_bf16.h>
#include <cuda_fp16.h>
#include <cstdint>
#include <math.h>

// Problem constants
#define BB   4
#define HH   1024
#define LL   8192
#define KD   64
#define KLEN 512      // KD * 2^(NS-1)

// ---------------- static device scratch ----------------
__device__ float g_k[HH * KLEN];                         // normalized kernel [h][t]
__device__ __half g_vh[(size_t)BB * HH * LL];            // gelu(conv+u*D) fp16 [b][h][l] (64 MB)
__device__ __half g_Wf[HH * HH];                         // W fp16 [o][h]

// ---------------- PTX helpers (baseline ISA only) ----------------
__device__ __forceinline__ uint32_t smem_u32(const void* p) {
    uint32_t a;
    asm("{ .reg .u64 t; cvta.to.shared.u64 t, %1; cvt.u32.u64 %0, t; }" : "=r"(a) : "l"(p));
    return a;
}
__device__ __forceinline__ void cp_async16(uint32_t sa, const void* g) {
    asm volatile("cp.async.cg.shared.global [%0], [%1], 16;" :: "r"(sa), "l"(g));
}
__device__ __forceinline__ void cp_commit() {
    asm volatile("cp.async.commit_group;" ::: "memory");
}
template<int N> __device__ __forceinline__ void cp_wait() {
    asm volatile("cp.async.wait_group %0;" :: "n"(N) : "memory");
}
__device__ __forceinline__ void ldmx4(uint32_t& r0, uint32_t& r1, uint32_t& r2, uint32_t& r3,
                                      uint32_t addr) {
    asm volatile("ldmatrix.sync.aligned.m8n8.x4.shared.b16 {%0,%1,%2,%3}, [%4];"
                 : "=r"(r0), "=r"(r1), "=r"(r2), "=r"(r3) : "r"(addr));
}
__device__ __forceinline__ void ldmx4t(uint32_t& r0, uint32_t& r1, uint32_t& r2, uint32_t& r3,
                                       uint32_t addr) {
    asm volatile("ldmatrix.sync.aligned.m8n8.x4.trans.shared.b16 {%0,%1,%2,%3}, [%4];"
                 : "=r"(r0), "=r"(r1), "=r"(r2), "=r"(r3) : "r"(addr));
}
__device__ __forceinline__ void mma16816h(float* c, const uint32_t* a, uint32_t b0, uint32_t b1) {
    asm volatile(
        "mma.sync.aligned.m16n8k16.row.col.f32.f16.f16.f32 "
        "{%0,%1,%2,%3}, {%4,%5,%6,%7}, {%8,%9}, {%0,%1,%2,%3};"
        : "+f"(c[0]), "+f"(c[1]), "+f"(c[2]), "+f"(c[3])
        : "r"(a[0]), "r"(a[1]), "r"(a[2]), "r"(a[3]), "r"(b0), "r"(b1));
}

// ============================================================
// Kernel 1: build combined, normalized conv kernel per head.
// ============================================================
__global__ void __launch_bounds__(128) build_k_kernel(
    const float* __restrict__ k0, const float* __restrict__ k1,
    const float* __restrict__ k2, const float* __restrict__ k3)
{
    int h   = blockIdx.x;
    int tid = threadIdx.x;
    const float* ks[4] = { k0 + h * KD, k1 + h * KD, k2 + h * KD, k3 + h * KD };

    float vals[4];
    float ss = 0.0f;
#pragma unroll
    for (int r = 0; r < 4; r++) {
        int t = tid + r * 128;
        float acc = 0.0f;
#pragma unroll
        for (int i = 0; i < 4; i++) {
            int len = KD << i;
            if (t < len) {
                float s = (float)(1 << i);
                float coord = (t + 0.5f) / s - 0.5f;
                coord = fminf(fmaxf(coord, 0.0f), 63.0f);
                int lo  = (int)floorf(coord);
                float w = coord - (float)lo;
                int hi  = min(lo + 1, 63);
                float val = ks[i][lo] * (1.0f - w) + ks[i][hi] * w;
                acc += val * (float)(1 << (3 - i));
            }
        }
        vals[r] = acc;
        ss += acc * acc;
    }

    __shared__ float red[128];
    red[tid] = ss;
    __syncthreads();
    for (int s = 64; s > 0; s >>= 1) {
        if (tid < s) red[tid] += red[tid + s];
        __syncthreads();
    }
    float inv = 1.0f / sqrtf(red[0]);
#pragma unroll
    for (int r = 0; r < 4; r++)
        g_k[h * KLEN + tid + r * 128] = vals[r] * inv;
}

// ============================================================
// Kernel 2: block-Toeplitz tensor-core conv + u*D + exact GELU -> g_vh (fp16)
// One CTA per (b,h). y_m = sum_{d=0}^{32} K_d u_{m-d},
// K_d[i][j] = k[16d+i-j].
// ============================================================
#define SM_U16  0                         // 17408 halves (512 zero pad + 8192)
#define SM_U32  34816                     // 8192 f32
#define SM_A    67584                     // 33 * 768 B (16 rows x 48B pitch)
#define SM_K    92928                     // 512 f32
#define SM_STG  94976                     // 8 warps * 1088 B
#define CONV_SMEM 103680

__global__ void __launch_bounds__(256) conv_mma_kernel(
    const float* __restrict__ u, const float* __restrict__ D)
{
    extern __shared__ __align__(128) char smem[];
    uint32_t sbase = smem_u32(smem);
    __half* u16 = reinterpret_cast<__half*>(smem + SM_U16);
    float*  u32 = reinterpret_cast<float*>(smem + SM_U32);
    __half* Atb = reinterpret_cast<__half*>(smem + SM_A);
    float*  kf  = reinterpret_cast<float*>(smem + SM_K);

    int bh  = blockIdx.x;
    int h   = bh & (HH - 1);
    int tid = threadIdx.x;
    int wid = tid >> 5, lane = tid & 31;

    // ---- load u row: fp32 copy + fp16 copy (with 512-half zero prefix) ----
    const float* ub = u + (size_t)bh * LL;
    if (tid < 128) {
        uint2 z = make_uint2(0u, 0u);
        *reinterpret_cast<uint2*>(u16 + tid * 4) = z;
    }
#pragma unroll 4
    for (int i = tid; i < LL / 4; i += 256) {
        float4 v4 = *reinterpret_cast<const float4*>(ub + i * 4);
        *reinterpret_cast<float4*>(u32 + i * 4) = v4;
        __half2 p0 = __floats2half2_rn(v4.x, v4.y);
        __half2 p1 = __floats2half2_rn(v4.z, v4.w);
        uint2 pk;
        pk.x = *reinterpret_cast<unsigned*>(&p0);
        pk.y = *reinterpret_cast<unsigned*>(&p1);
        *reinterpret_cast<uint2*>(u16 + KLEN + i * 4) = pk;
    }
    kf[tid]       = g_k[h * KLEN + tid];
    kf[tid + 256] = g_k[h * KLEN + tid + 256];
    __syncthreads();

    // ---- build Toeplitz table: Atb[d][i][j] = k[16d+i-j] ----
    {
        int i_ = tid >> 4, j_ = tid & 15;
#pragma unroll
        for (int d = 0; d < 33; d++) {
            int tau = d * 16 + i_ - j_;
            __half val = (tau >= 0 && tau < KLEN) ? __float2half(kf[tau]) : __half(0);
            Atb[d * 384 + i_ * 24 + j_] = val;
        }
    }
    __syncthreads();

    // ---- main MMA loop ----
    int a_row = (lane & 7) + ((lane >> 3) & 1) * 8;
    int a_cb  = (lane >> 4) * 16;
    int b_nrow = (lane >> 4) * 8 + (lane & 7);
    int b_cb  = ((lane >> 3) & 1) * 16;

    uint32_t aBase = sbase + SM_A + a_row * 48 + a_cb;
    uint32_t uBase = sbase + SM_U16 + 1024 + 32 * (wid * 64 + b_nrow) + b_cb;

    float acc[4][2][4];
#pragma unroll
    for (int t = 0; t < 4; t++)
#pragma unroll
        for (int mm = 0; mm < 2; mm++)
#pragma unroll
            for (int r = 0; r < 4; r++) acc[t][mm][r] = 0.0f;

    for (int d = 0; d < 33; d++) {
        uint32_t af[4];
        ldmx4(af[0], af[1], af[2], af[3], aBase + d * 768);
        uint32_t ub0 = uBase - 32 * d;
#pragma unroll
        for (int t = 0; t < 4; t++) {
            uint32_t b0, b1, b2, b3;
            ldmx4(b0, b1, b2, b3, ub0 + t * 512);
            mma16816h(acc[t][0], af, b0, b1);
            mma16816h(acc[t][1], af, b2, b3);
        }
    }

    // ---- epilogue: stage -> +u*D -> exact GELU -> g_vh fp16 (coalesced) ----
    float Dh = D[h];
    float* st = reinterpret_cast<float*>(smem + SM_STG) + wid * 272;
    __half* vb = g_vh + (size_t)bh * LL;
    int ir = lane >> 2;
    int c0 = (lane & 3) * 2;

#pragma unroll
    for (int t = 0; t < 4; t++) {
#pragma unroll
        for (int mm = 0; mm < 2; mm++) {
            st[ir * 17 + mm * 8 + c0]           = acc[t][mm][0];
            st[ir * 17 + mm * 8 + c0 + 1]       = acc[t][mm][1];
            st[(ir + 8) * 17 + mm * 8 + c0]     = acc[t][mm][2];
            st[(ir + 8) * 17 + mm * 8 + c0 + 1] = acc[t][mm][3];
        }
        __syncwarp();
        int lbase = wid * 1024 + t * 256 + lane * 8;
        float o8[8];
#pragma unroll
        for (int r = 0; r < 8; r++) {
            int l_loc = lane * 8 + r;
            float y = st[(l_loc & 15) * 17 + (l_loc >> 4)];
            float x = y + u32[lbase + r] * Dh;
            o8[r] = 0.5f * x * (1.0f + erff(x * 0.70710678118654752f));
        }
        __half2 h0 = __floats2half2_rn(o8[0], o8[1]);
        __half2 h1 = __floats2half2_rn(o8[2], o8[3]);
        __half2 h2 = __floats2half2_rn(o8[4], o8[5]);
        __half2 h3 = __floats2half2_rn(o8[6], o8[7]);
        uint4 pk;
        pk.x = *reinterpret_cast<unsigned*>(&h0);
        pk.y = *reinterpret_cast<unsigned*>(&h1);
        pk.z = *reinterpret_cast<unsigned*>(&h2);
        pk.w = *reinterpret_cast<unsigned*>(&h3);
        *reinterpret_cast<uint4*>(vb + lbase) = pk;
        __syncwarp();
    }
}

// ============================================================
// Kernel 3: W f32 -> fp16 (same layout [o][h])
// ============================================================
__global__ void __launch_bounds__(256) wconv_kernel(const float* __restrict__ W)
{
    int base = (blockIdx.x * 256 + threadIdx.x) * 4;
#pragma unroll
    for (int i = 0; i < 4; i++)
        g_Wf[base + i] = __float2half(W[base + i]);
}

// ============================================================
// Kernel 4: mma.sync fp16 GEMM, B read directly from [b][h][l] via ldmatrix.trans
// C[b,o,l] = sum_h W[o,h] v[h,l] + bias[o]
// CTA 128(o) x 256(l), 8 warps (2m x 4n), warp tile 64x64.
// K chunks of 32, 4-stage cp.async, 108.5 KB smem -> 2 CTAs/SM.
// ============================================================
#define NCH     32
#define GSTAGES 4
#define AROWB   80                        // A: 128 rows, 64B data + pad
#define BROWB   528                       // B: 32 h-rows, 512B data + 16B pad
#define A_SZ    (128 * AROWB)             // 10240
#define B_SZ    (32 * BROWB)              // 16896
#define STG_SZ  (A_SZ + B_SZ)             // 27136
static constexpr unsigned GEMM_SMEM = GSTAGES * STG_SZ;   // 108544

__device__ __forceinline__ void gemm_load_chunk(
    uint32_t sbase, int stage, int chunk, int o0, int b, int l0, int tid)
{
    int h0 = chunk * 32;
    uint32_t a_s = sbase + stage * STG_SZ;
    uint32_t b_s = a_s + A_SZ;

    // A: W [o][h], 128 rows x 64B
#pragma unroll
    for (int u = 0; u < 2; u++) {
        int idx = tid + u * 256;          // 0..511
        int row = idx >> 2, c = idx & 3;
        const char* g = reinterpret_cast<const char*>(
            g_Wf + (size_t)(o0 + row) * HH + h0) + c * 16;
        cp_async16(a_s + row * AROWB + c * 16, g);
    }
    // B: v [h][l], 32 rows x 512B
#pragma unroll
    for (int u = 0; u < 4; u++) {
        int idx = tid + u * 256;          // 0..1023
        int row = idx >> 5, c = idx & 31;
        const char* g = reinterpret_cast<const char*>(
            g_vh + ((size_t)(b * HH + h0 + row)) * LL + l0) + c * 16;
        cp_async16(b_s + row * BROWB + c * 16, g);
    }
    cp_commit();
}

__global__ void __launch_bounds__(256) mma_gemm_kernel(
    const float* __restrict__ bias, float* __restrict__ out)
{
    extern __shared__ __align__(128) char smem[];
    uint32_t sbase = smem_u32(smem);
    int tid  = threadIdx.x;
    int wid  = tid >> 5, lane = tid & 31;
    int o0 = blockIdx.x * 128;            // o-tiles fastest -> B tile shared in L2
    int l0 = blockIdx.y * 256;
    int b  = blockIdx.z;

    int wm = wid & 1;
    int wn = wid >> 1;

    int a_row = ((lane >> 3) & 1) * 8 + (lane & 7);
    int a_cb  = (lane >> 4) * 16;
    // B via ldmatrix.trans from [k=h][n=l] rows
    int bk_row = (lane & 7) + ((lane >> 3) & 1) * 8;     // k-row within 16
    int bn_off = (lane >> 4) * 16;                       // n byte offset (8 halves)

    float acc[4][8][4];
#pragma unroll
    for (int mi = 0; mi < 4; mi++)
#pragma unroll
        for (int ni = 0; ni < 8; ni++)
#pragma unroll
            for (int r = 0; r < 4; r++) acc[mi][ni][r] = 0.0f;

    gemm_load_chunk(sbase, 0, 0, o0, b, l0, tid);
    gemm_load_chunk(sbase, 1, 1, o0, b, l0, tid);
    gemm_load_chunk(sbase, 2, 2, o0, b, l0, tid);

    for (int i = 0; i < NCH; i++) {
        if (i < NCH - 3) { cp_wait<2>(); } else { cp_wait<0>(); }
        __syncthreads();

        if (i + 3 < NCH)
            gemm_load_chunk(sbase, (i + 3) & 3, i + 3, o0, b, l0, tid);

        uint32_t a_s = sbase + (i & 3) * STG_SZ;
        uint32_t b_s = a_s + A_SZ;

#pragma unroll
        for (int ks = 0; ks < 2; ks++) {
            uint32_t afrag[4][4];
#pragma unroll
            for (int mi = 0; mi < 4; mi++) {
                uint32_t addr = a_s + (wm * 64 + mi * 16 + a_row) * AROWB
                              + a_cb + ks * 32;
                ldmx4(afrag[mi][0], afrag[mi][1], afrag[mi][2], afrag[mi][3], addr);
            }
            uint32_t bfrag[4][4];
#pragma unroll
            for (int n2 = 0; n2 < 4; n2++) {
                uint32_t addr = b_s + (ks * 16 + bk_row) * BROWB
                              + (wn * 64 + n2 * 16) * 2 + bn_off;
                ldmx4t(bfrag[n2][0], bfrag[n2][1], bfrag[n2][2], bfrag[n2][3], addr);
            }
#pragma unroll
            for (int mi = 0; mi < 4; mi++)
#pragma unroll
                for (int ni = 0; ni < 8; ni++)
                    mma16816h(acc[mi][ni], afrag[mi],
                              bfrag[ni >> 1][(ni & 1) * 2],
                              bfrag[ni >> 1][(ni & 1) * 2 + 1]);
        }
    }
    __syncthreads();

#pragma unroll
    for (int mi = 0; mi < 4; mi++) {
        int o_a = o0 + wm * 64 + mi * 16 + (lane >> 2);
        int o_b = o_a + 8;
        float bo_a = __ldg(bias + o_a);
        float bo_b = __ldg(bias + o_b);
#pragma unroll
        for (int ni = 0; ni < 8; ni++) {
            int l = l0 + wn * 64 + ni * 8 + (lane & 3) * 2;
            float2 v0 = make_float2(acc[mi][ni][0] + bo_a, acc[mi][ni][1] + bo_a);
            float2 v1 = make_float2(acc[mi][ni][2] + bo_b, acc[mi][ni][3] + bo_b);
            *reinterpret_cast<float2*>(out + ((size_t)(b * HH + o_a)) * LL + l) = v0;
            *reinterpret_cast<float2*>(out + ((size_t)(b * HH + o_b)) * LL + l) = v1;
        }
    }
}

// ============================================================
extern "C" void kernel_launch(void* const* d_in, const int* in_sizes, int n_in,
                              void* d_out, int out_size)
{
    (void)in_sizes; (void)n_in; (void)out_size;
    const float* u    = (const float*)d_in[0];
    const float* k0   = (const float*)d_in[1];
    const float* k1   = (const float*)d_in[2];
    const float* k2   = (const float*)d_in[3];
    const float* k3   = (const float*)d_in[4];
    const float* D    = (const float*)d_in[5];
    const float* W    = (const float*)d_in[6];
    const float* bias = (const float*)d_in[7];
    float* out = (float*)d_out;

    cudaFuncSetAttribute(mma_gemm_kernel,
                         cudaFuncAttributeMaxDynamicSharedMemorySize, GEMM_SMEM);
    cudaFuncSetAttribute(conv_mma_kernel,
                         cudaFuncAttributeMaxDynamicSharedMemorySize, CONV_SMEM);

    build_k_kernel<<<HH, 128>>>(k0, k1, k2, k3);
    conv_mma_kernel<<<BB * HH, 256, CONV_SMEM>>>(u, D);
    wconv_kernel<<<(HH * HH) / 1024, 256>>>(W);
    mma_gemm_kernel<<<dim3(HH / 128, LL / 256, BB), 256, GEMM_SMEM>>>(bias, out);
}

// round 17
// speedup vs baseline: 4.6416x; 1.0852x over previous
#include <cuda_runtime.h>
#include <cuda_bf16.h>
#include <cuda_fp16.h>
#include <cstdint>
#include <math.h>

// Problem constants
#define BB   4
#define HH   1024
#define LL   8192
#define KD   64
#define KLEN 512      // KD * 2^(NS-1)

// ---------------- static device scratch ----------------
__device__ float g_k[HH * KLEN];                         // normalized kernel [h][t]
__device__ __half g_vh[(size_t)BB * HH * LL];            // gelu(conv+u*D) fp16 [b][h][l] (64 MB)
__device__ __half g_Wf[HH * HH];                         // W fp16 [o][h]

// ---------------- PTX helpers (baseline ISA only) ----------------
__device__ __forceinline__ uint32_t smem_u32(const void* p) {
    uint32_t a;
    asm("{ .reg .u64 t; cvta.to.shared.u64 t, %1; cvt.u32.u64 %0, t; }" : "=r"(a) : "l"(p));
    return a;
}
__device__ __forceinline__ void cp_async16(uint32_t sa, const void* g) {
    asm volatile("cp.async.cg.shared.global [%0], [%1], 16;" :: "r"(sa), "l"(g));
}
__device__ __forceinline__ void cp_commit() {
    asm volatile("cp.async.commit_group;" ::: "memory");
}
template<int N> __device__ __forceinline__ void cp_wait() {
    asm volatile("cp.async.wait_group %0;" :: "n"(N) : "memory");
}
__device__ __forceinline__ void ldmx4(uint32_t& r0, uint32_t& r1, uint32_t& r2, uint32_t& r3,
                                      uint32_t addr) {
    asm volatile("ldmatrix.sync.aligned.m8n8.x4.shared.b16 {%0,%1,%2,%3}, [%4];"
                 : "=r"(r0), "=r"(r1), "=r"(r2), "=r"(r3) : "r"(addr));
}
__device__ __forceinline__ void ldmx4t(uint32_t& r0, uint32_t& r1, uint32_t& r2, uint32_t& r3,
                                       uint32_t addr) {
    asm volatile("ldmatrix.sync.aligned.m8n8.x4.trans.shared.b16 {%0,%1,%2,%3}, [%4];"
                 : "=r"(r0), "=r"(r1), "=r"(r2), "=r"(r3) : "r"(addr));
}
__device__ __forceinline__ void mma16816h(float* c, const uint32_t* a, uint32_t b0, uint32_t b1) {
    asm volatile(
        "mma.sync.aligned.m16n8k16.row.col.f32.f16.f16.f32 "
        "{%0,%1,%2,%3}, {%4,%5,%6,%7}, {%8,%9}, {%0,%1,%2,%3};"
        : "+f"(c[0]), "+f"(c[1]), "+f"(c[2]), "+f"(c[3])
        : "r"(a[0]), "r"(a[1]), "r"(a[2]), "r"(a[3]), "r"(b0), "r"(b1));
}

// ============================================================
// Kernel 1: build combined, normalized conv kernel per head.
// ============================================================
__global__ void __launch_bounds__(128) build_k_kernel(
    const float* __restrict__ k0, const float* __restrict__ k1,
    const float* __restrict__ k2, const float* __restrict__ k3)
{
    int h   = blockIdx.x;
    int tid = threadIdx.x;
    const float* ks[4] = { k0 + h * KD, k1 + h * KD, k2 + h * KD, k3 + h * KD };

    float vals[4];
    float ss = 0.0f;
#pragma unroll
    for (int r = 0; r < 4; r++) {
        int t = tid + r * 128;
        float acc = 0.0f;
#pragma unroll
        for (int i = 0; i < 4; i++) {
            int len = KD << i;
            if (t < len) {
                float s = (float)(1 << i);
                float coord = (t + 0.5f) / s - 0.5f;
                coord = fminf(fmaxf(coord, 0.0f), 63.0f);
                int lo  = (int)floorf(coord);
                float w = coord - (float)lo;
                int hi  = min(lo + 1, 63);
                float val = ks[i][lo] * (1.0f - w) + ks[i][hi] * w;
                acc += val * (float)(1 << (3 - i));
            }
        }
        vals[r] = acc;
        ss += acc * acc;
    }

    __shared__ float red[128];
    red[tid] = ss;
    __syncthreads();
    for (int s = 64; s > 0; s >>= 1) {
        if (tid < s) red[tid] += red[tid + s];
        __syncthreads();
    }
    float inv = 1.0f / sqrtf(red[0]);
#pragma unroll
    for (int r = 0; r < 4; r++)
        g_k[h * KLEN + tid + r * 128] = vals[r] * inv;
}

// ============================================================
// Kernel 2: block-Toeplitz tensor-core conv + u*D + exact GELU -> g_vh (fp16)
// One CTA per (b,h). 2 CTAs/SM (regs capped at 128).
// ============================================================
#define SM_U16  0                         // 17408 halves (512 zero pad + 8192)
#define SM_U32  34816                     // 8192 f32
#define SM_A    67584                     // 33 * 768 B (16 rows x 48B pitch)
#define SM_K    92928                     // 512 f32
#define SM_STG  94976                     // 8 warps * 1088 B
#define CONV_SMEM 103680

__global__ void __launch_bounds__(256, 2) conv_mma_kernel(
    const float* __restrict__ u, const float* __restrict__ D)
{
    extern __shared__ __align__(128) char smem[];
    uint32_t sbase = smem_u32(smem);
    __half* u16 = reinterpret_cast<__half*>(smem + SM_U16);
    float*  u32 = reinterpret_cast<float*>(smem + SM_U32);
    __half* Atb = reinterpret_cast<__half*>(smem + SM_A);
    float*  kf  = reinterpret_cast<float*>(smem + SM_K);

    int bh  = blockIdx.x;
    int h   = bh & (HH - 1);
    int tid = threadIdx.x;
    int wid = tid >> 5, lane = tid & 31;

    // ---- load u row: fp32 copy + fp16 copy (with 512-half zero prefix) ----
    const float* ub = u + (size_t)bh * LL;
    if (tid < 128) {
        uint2 z = make_uint2(0u, 0u);
        *reinterpret_cast<uint2*>(u16 + tid * 4) = z;
    }
#pragma unroll 4
    for (int i = tid; i < LL / 4; i += 256) {
        float4 v4 = *reinterpret_cast<const float4*>(ub + i * 4);
        *reinterpret_cast<float4*>(u32 + i * 4) = v4;
        __half2 p0 = __floats2half2_rn(v4.x, v4.y);
        __half2 p1 = __floats2half2_rn(v4.z, v4.w);
        uint2 pk;
        pk.x = *reinterpret_cast<unsigned*>(&p0);
        pk.y = *reinterpret_cast<unsigned*>(&p1);
        *reinterpret_cast<uint2*>(u16 + KLEN + i * 4) = pk;
    }
    kf[tid]       = g_k[h * KLEN + tid];
    kf[tid + 256] = g_k[h * KLEN + tid + 256];
    __syncthreads();

    // ---- build Toeplitz table: Atb[d][i][j] = k[16d+i-j] ----
    {
        int i_ = tid >> 4, j_ = tid & 15;
#pragma unroll
        for (int d = 0; d < 33; d++) {
            int tau = d * 16 + i_ - j_;
            __half val = (tau >= 0 && tau < KLEN) ? __float2half(kf[tau]) : __half(0);
            Atb[d * 384 + i_ * 24 + j_] = val;
        }
    }
    __syncthreads();

    // ---- main MMA loop ----
    int a_row = (lane & 7) + ((lane >> 3) & 1) * 8;
    int a_cb  = (lane >> 4) * 16;
    int b_nrow = (lane >> 4) * 8 + (lane & 7);
    int b_cb  = ((lane >> 3) & 1) * 16;

    uint32_t aBase = sbase + SM_A + a_row * 48 + a_cb;
    uint32_t uBase = sbase + SM_U16 + 1024 + 32 * (wid * 64 + b_nrow) + b_cb;

    float acc[4][2][4];
#pragma unroll
    for (int t = 0; t < 4; t++)
#pragma unroll
        for (int mm = 0; mm < 2; mm++)
#pragma unroll
            for (int r = 0; r < 4; r++) acc[t][mm][r] = 0.0f;

    for (int d = 0; d < 33; d++) {
        uint32_t af[4];
        ldmx4(af[0], af[1], af[2], af[3], aBase + d * 768);
        uint32_t ub0 = uBase - 32 * d;
#pragma unroll
        for (int t = 0; t < 4; t++) {
            uint32_t b0, b1, b2, b3;
            ldmx4(b0, b1, b2, b3, ub0 + t * 512);
            mma16816h(acc[t][0], af, b0, b1);
            mma16816h(acc[t][1], af, b2, b3);
        }
    }

    // ---- epilogue: stage -> +u*D -> exact GELU -> g_vh fp16 (coalesced) ----
    float Dh = D[h];
    float* st = reinterpret_cast<float*>(smem + SM_STG) + wid * 272;
    __half* vb = g_vh + (size_t)bh * LL;
    int ir = lane >> 2;
    int c0 = (lane & 3) * 2;

#pragma unroll
    for (int t = 0; t < 4; t++) {
#pragma unroll
        for (int mm = 0; mm < 2; mm++) {
            st[ir * 17 + mm * 8 + c0]           = acc[t][mm][0];
            st[ir * 17 + mm * 8 + c0 + 1]       = acc[t][mm][1];
            st[(ir + 8) * 17 + mm * 8 + c0]     = acc[t][mm][2];
            st[(ir + 8) * 17 + mm * 8 + c0 + 1] = acc[t][mm][3];
        }
        __syncwarp();
        int lbase = wid * 1024 + t * 256 + lane * 8;
        float o8[8];
#pragma unroll
        for (int r = 0; r < 8; r++) {
            int l_loc = lane * 8 + r;
            float y = st[(l_loc & 15) * 17 + (l_loc >> 4)];
            float x = y + u32[lbase + r] * Dh;
            o8[r] = 0.5f * x * (1.0f + erff(x * 0.70710678118654752f));
        }
        __half2 h0 = __floats2half2_rn(o8[0], o8[1]);
        __half2 h1 = __floats2half2_rn(o8[2], o8[3]);
        __half2 h2 = __floats2half2_rn(o8[4], o8[5]);
        __half2 h3 = __floats2half2_rn(o8[6], o8[7]);
        uint4 pk;
        pk.x = *reinterpret_cast<unsigned*>(&h0);
        pk.y = *reinterpret_cast<unsigned*>(&h1);
        pk.z = *reinterpret_cast<unsigned*>(&h2);
        pk.w = *reinterpret_cast<unsigned*>(&h3);
        *reinterpret_cast<uint4*>(vb + lbase) = pk;
        __syncwarp();
    }
}

// ============================================================
// Kernel 3: W f32 -> fp16 (same layout [o][h])
// ============================================================
__global__ void __launch_bounds__(256) wconv_kernel(const float* __restrict__ W)
{
    int base = (blockIdx.x * 256 + threadIdx.x) * 4;
#pragma unroll
    for (int i = 0; i < 4; i++)
        g_Wf[base + i] = __float2half(W[base + i]);
}

// ============================================================
// Kernel 4: mma.sync fp16 GEMM, trans-B from [b][h][l].
// CTA 128(o) x 128(l), warp tile 64x32, 8 warps (2m x 4n).
// 4-stage cp.async, 75.8 KB smem, <=128 regs -> 2 CTAs/SM.
// ============================================================
#define NCH     32
#define GSTAGES 4
#define AROWB   80                        // A: 128 rows, 64B data + pad
#define BROWB   272                       // B: 32 h-rows, 256B data + 16B pad
#define A_SZ    (128 * AROWB)             // 10240
#define B_SZ    (32 * BROWB)              // 8704
#define STG_SZ  (A_SZ + B_SZ)             // 18944
static constexpr unsigned GEMM_SMEM = GSTAGES * STG_SZ;   // 75776

__device__ __forceinline__ void gemm_load_chunk(
    uint32_t sbase, int stage, int chunk, int o0, int b, int l0, int tid)
{
    int h0 = chunk * 32;
    uint32_t a_s = sbase + stage * STG_SZ;
    uint32_t b_s = a_s + A_SZ;

    // A: W [o][h], 128 rows x 64B
#pragma unroll
    for (int u = 0; u < 2; u++) {
        int idx = tid + u * 256;          // 0..511
        int row = idx >> 2, c = idx & 3;
        const char* g = reinterpret_cast<const char*>(
            g_Wf + (size_t)(o0 + row) * HH + h0) + c * 16;
        cp_async16(a_s + row * AROWB + c * 16, g);
    }
    // B: v [h][l], 32 rows x 256B
#pragma unroll
    for (int u = 0; u < 2; u++) {
        int idx = tid + u * 256;          // 0..511
        int row = idx >> 4, c = idx & 15;
        const char* g = reinterpret_cast<const char*>(
            g_vh + ((size_t)(b * HH + h0 + row)) * LL + l0) + c * 16;
        cp_async16(b_s + row * BROWB + c * 16, g);
    }
    cp_commit();
}

__global__ void __launch_bounds__(256, 2) mma_gemm_kernel(
    const float* __restrict__ bias, float* __restrict__ out)
{
    extern __shared__ __align__(128) char smem[];
    uint32_t sbase = smem_u32(smem);
    int tid  = threadIdx.x;
    int wid  = tid >> 5, lane = tid & 31;
    int o0 = blockIdx.x * 128;            // o-tiles fastest -> B tile shared in L2
    int l0 = blockIdx.y * 128;
    int b  = blockIdx.z;

    int wm = wid & 1;                     // m offset 64*wm
    int wn = wid >> 1;                    // n offset 32*wn

    int a_row = ((lane >> 3) & 1) * 8 + (lane & 7);
    int a_cb  = (lane >> 4) * 16;
    // B via ldmatrix.trans from [k=h][n=l] rows
    int bk_row = (lane & 7) + ((lane >> 3) & 1) * 8;
    int bn_off = (lane >> 4) * 16;

    float acc[4][4][4];
#pragma unroll
    for (int mi = 0; mi < 4; mi++)
#pragma unroll
        for (int ni = 0; ni < 4; ni++)
#pragma unroll
            for (int r = 0; r < 4; r++) acc[mi][ni][r] = 0.0f;

    gemm_load_chunk(sbase, 0, 0, o0, b, l0, tid);
    gemm_load_chunk(sbase, 1, 1, o0, b, l0, tid);
    gemm_load_chunk(sbase, 2, 2, o0, b, l0, tid);

    for (int i = 0; i < NCH; i++) {
        if (i < NCH - 3) { cp_wait<2>(); } else { cp_wait<0>(); }
        __syncthreads();

        if (i + 3 < NCH)
            gemm_load_chunk(sbase, (i + 3) & 3, i + 3, o0, b, l0, tid);

        uint32_t a_s = sbase + (i & 3) * STG_SZ;
        uint32_t b_s = a_s + A_SZ;

#pragma unroll
        for (int ks = 0; ks < 2; ks++) {
            uint32_t afrag[4][4];
#pragma unroll
            for (int mi = 0; mi < 4; mi++) {
                uint32_t addr = a_s + (wm * 64 + mi * 16 + a_row) * AROWB
                              + a_cb + ks * 32;
                ldmx4(afrag[mi][0], afrag[mi][1], afrag[mi][2], afrag[mi][3], addr);
            }
            uint32_t bfrag[2][4];
#pragma unroll
            for (int n2 = 0; n2 < 2; n2++) {
                uint32_t addr = b_s + (ks * 16 + bk_row) * BROWB
                              + (wn * 32 + n2 * 16) * 2 + bn_off;
                ldmx4t(bfrag[n2][0], bfrag[n2][1], bfrag[n2][2], bfrag[n2][3], addr);
            }
#pragma unroll
            for (int mi = 0; mi < 4; mi++)
#pragma unroll
                for (int ni = 0; ni < 4; ni++)
                    mma16816h(acc[mi][ni], afrag[mi],
                              bfrag[ni >> 1][(ni & 1) * 2],
                              bfrag[ni >> 1][(ni & 1) * 2 + 1]);
        }
    }
    __syncthreads();

#pragma unroll
    for (int mi = 0; mi < 4; mi++) {
        int o_a = o0 + wm * 64 + mi * 16 + (lane >> 2);
        int o_b = o_a + 8;
        float bo_a = __ldg(bias + o_a);
        float bo_b = __ldg(bias + o_b);
#pragma unroll
        for (int ni = 0; ni < 4; ni++) {
            int l = l0 + wn * 32 + ni * 8 + (lane & 3) * 2;
            float2 v0 = make_float2(acc[mi][ni][0] + bo_a, acc[mi][ni][1] + bo_a);
            float2 v1 = make_float2(acc[mi][ni][2] + bo_b, acc[mi][ni][3] + bo_b);
            *reinterpret_cast<float2*>(out + ((size_t)(b * HH + o_a)) * LL + l) = v0;
            *reinterpret_cast<float2*>(out + ((size_t)(b * HH + o_b)) * LL + l) = v1;
        }
    }
}

// ============================================================
extern "C" void kernel_launch(void* const* d_in, const int* in_sizes, int n_in,
                              void* d_out, int out_size)
{
    (void)in_sizes; (void)n_in; (void)out_size;
    const float* u    = (const float*)d_in[0];
    const float* k0   = (const float*)d_in[1];
    const float* k1   = (const float*)d_in[2];
    const float* k2   = (const float*)d_in[3];
    const float* k3   = (const float*)d_in[4];
    const float* D    = (const float*)d_in[5];
    const float* W    = (const float*)d_in[6];
    const float* bias = (const float*)d_in[7];
    float* out = (float*)d_out;

    cudaFuncSetAttribute(mma_gemm_kernel,
                         cudaFuncAttributeMaxDynamicSharedMemorySize, GEMM_SMEM);
    cudaFuncSetAttribute(conv_mma_kernel,
                         cudaFuncAttributeMaxDynamicSharedMemorySize, CONV_SMEM);

    build_k_kernel<<<HH, 128>>>(k0, k1, k2, k3);
    conv_mma_kernel<<<BB * HH, 256, CONV_SMEM>>>(u, D);
    wconv_kernel<<<(HH * HH) / 1024, 256>>>(W);
    mma_gemm_kernel<<<dim3(HH / 128, LL / 128, BB), 256, GEMM_SMEM>>>(bias, out);
}